// round 12
// baseline (speedup 1.0000x reference)
#include <cuda_runtime.h>
#include <cuda_bf16.h>
#include <cstdint>

#define Bn 8192
#define Dn 256
#define INn 64
#define ONn 256

typedef unsigned int u32;
typedef unsigned short u16;

// A matrix (inner acts) as packed bf16 pairs: [b][d/2], low half = even d
__device__ __align__(16) u32 g_Ah[(size_t)Bn * (Dn / 2)];   // 4MB
__device__ __align__(16) u32 g_Al[(size_t)Bn * (Dn / 2)];   // 4MB

__device__ __forceinline__ u32 smem_u32(const void* p) {
    u32 a;
    asm("{ .reg .u64 t; cvta.to.shared.u64 t, %1; cvt.u32.u64 %0, t; }" : "=r"(a) : "l"(p));
    return a;
}
__device__ __forceinline__ void ldm4(u32* r, u32 addr) {
    asm volatile("ldmatrix.sync.aligned.m8n8.x4.shared.b16 {%0,%1,%2,%3}, [%4];"
                 : "=r"(r[0]), "=r"(r[1]), "=r"(r[2]), "=r"(r[3]) : "r"(addr));
}
__device__ __forceinline__ void mma_bf16(float* d, const u32* a, u32 b0, u32 b1) {
    asm volatile("mma.sync.aligned.m16n8k16.row.col.f32.bf16.bf16.f32 "
                 "{%0,%1,%2,%3}, {%4,%5,%6,%7}, {%8,%9}, {%0,%1,%2,%3};"
                 : "+f"(d[0]), "+f"(d[1]), "+f"(d[2]), "+f"(d[3])
                 : "r"(a[0]), "r"(a[1]), "r"(a[2]), "r"(a[3]), "r"(b0), "r"(b1));
}
__device__ __forceinline__ void bsplit(float v, u16& h, u16& l) {
    __nv_bfloat16 hb = __float2bfloat16(v);
    h = __bfloat16_as_ushort(hb);
    l = __bfloat16_as_ushort(__float2bfloat16(v - __bfloat162float(hb)));
}

// ---------------------------------------------------------------------------
// kan_eval (prep fused): grid (B/512, D/16) = (16,16), 256 threads, occ 2.
// Phase P (LUT build, 16 d per block): rank-sort 64 breakpoints per d +
//   shfl scans (same math as verified R9 prep).
// Phase E: binary-search PWL eval, warp w owns d rows 2w / 2w+1 x 512 b,
//   packs bf16 hi/lo pairs in-lane, stages, coalesced store to g_Ah/g_Al.
// smem: region1 (sT 16x64 + sSC 16x65 float2) persistent,
//       region2 = union(LUT temps 6240f, x tile 16x520, staging 9216 u32).
// ---------------------------------------------------------------------------
#define R2OFF 3104
#define EVAL_SMEM ((R2OFF + 9216) * 4)   // 49280 bytes

__global__ __launch_bounds__(256, 2) void kan_eval(
    const float* __restrict__ x,
    const float* __restrict__ w1, const float* __restrict__ b1,
    const float* __restrict__ w2, const float* __restrict__ b2)
{
    extern __shared__ float sm[];
    float*  sT  = sm;                        // [16][64] sorted breakpoints
    float2* sSC = (float2*)(sm + 1024);      // [16][65] segment (S,C)
    float*  r2  = sm + R2OFF;
    // region2 aliases
    float* skey = r2;                        // [16][65]
    float* sdS  = r2 + 1040;
    float* sdC  = r2 + 2080;
    float* ssK  = r2 + 3120;                 // [16][65] sorted
    float* ssS  = r2 + 4160;
    float* ssC  = r2 + 5200;
    float* sx   = r2;                        // [16][520]
    u32*  stgH  = (u32*)r2;                  // [512][9]
    u32*  stgL  = (u32*)r2 + 4608;

    const int t = threadIdx.x;
    const int lane = t & 31, w = t >> 5;
    const int b0 = blockIdx.x << 9;          // *512
    const int d0 = blockIdx.y << 4;          // *16

    // ---------------- Phase P: LUT build ----------------
    // Step A: raw breakpoints. thread t -> d row (t>>4), i = (t&15)*4 .. +3
    const int dl = t >> 4;
    const int i0 = (t & 15) << 2;
    float key[4], dS[4], dC[4];
    float myBS = 0.f, myBC = 0.f;
    {
        const int base = (d0 + dl) * INn + i0;
        const float4 w4 = *(const float4*)(w1 + base);
        const float4 b4 = *(const float4*)(b1 + base);
        const float4 v4 = *(const float4*)(w2 + base);
        const float* wf = (const float*)&w4;
        const float* bf = (const float*)&b4;
        const float* vf = (const float*)&v4;
        #pragma unroll
        for (int q = 0; q < 4; ++q) {
            const float ww = wf[q], bb = bf[q], vv = vf[q];
            if (ww == 0.f) {
                key[q] = __int_as_float(0x7f800000);
                dS[q] = 0.f; dC[q] = 0.f;
                myBC += fmaxf(bb, 0.f) * vv;
            } else {
                key[q] = -bb / ww;
                const float pS = ww * vv, pC = bb * vv;
                if (ww > 0.f) { dS[q] = pS;  dC[q] = pC; }
                else          { dS[q] = -pS; dC[q] = -pC; myBS += pS; myBC += pC; }
            }
            skey[dl * 65 + i0 + q] = key[q];
        }
    }
    // base reduce within 16-lane halves (lanes of same d row)
    #pragma unroll
    for (int off = 8; off >= 1; off >>= 1) {
        myBS += __shfl_xor_sync(~0u, myBS, off);
        myBC += __shfl_xor_sync(~0u, myBC, off);
    }
    __syncthreads();

    // Step B: rank + scatter (stable)
    #pragma unroll
    for (int q = 0; q < 4; ++q) {
        const float kq = key[q];
        const int iq = i0 + q;
        int rank = 0;
        const float* row = skey + dl * 65;
        #pragma unroll
        for (int j = 0; j < 64; ++j) {
            const float tj = row[j];
            rank += (tj < kq || (tj == kq && j < iq)) ? 1 : 0;
        }
        ssK[dl * 65 + rank] = kq;
        ssS[dl * 65 + rank] = dS[q];
        ssC[dl * 65 + rank] = dC[q];
    }
    __syncthreads();

    // Step C: per-warp scans for d rows 2w and 2w+1
    #pragma unroll
    for (int h = 0; h < 2; ++h) {
        const int dd = (w << 1) + h;
        float s0 = ssS[dd * 65 + lane], s1 = ssS[dd * 65 + lane + 32];
        float c0 = ssC[dd * 65 + lane], c1 = ssC[dd * 65 + lane + 32];
        #pragma unroll
        for (int off = 1; off < 32; off <<= 1) {
            const float a0 = __shfl_up_sync(~0u, s0, off);
            const float a1 = __shfl_up_sync(~0u, c0, off);
            const float a2 = __shfl_up_sync(~0u, s1, off);
            const float a3 = __shfl_up_sync(~0u, c1, off);
            if (lane >= off) { s0 += a0; c0 += a1; s1 += a2; c1 += a3; }
        }
        s1 += __shfl_sync(~0u, s0, 31);
        c1 += __shfl_sync(~0u, c0, 31);
        // base for row dd lives in lane h*16 (dl = 2w + (lane>>4))
        float bS = __shfl_sync(~0u, myBS, h << 4);
        float bC = __shfl_sync(~0u, myBC, h << 4);
        bC += __ldg(b2 + d0 + dd);
        sT[(dd << 6) + lane]      = ssK[dd * 65 + lane];
        sT[(dd << 6) + lane + 32] = ssK[dd * 65 + lane + 32];
        if (lane == 0) sSC[dd * 65] = make_float2(bS, bC);
        sSC[dd * 65 + 1 + lane]  = make_float2(bS + s0, bC + c0);
        sSC[dd * 65 + 33 + lane] = make_float2(bS + s1, bC + c1);
    }
    __syncthreads();

    // ---------------- Phase E: x load (transposed) ----------------
    for (int k = t; k < 2048; k += 256) {
        const int b = k >> 2, c4 = (k & 3) << 2;
        const float4 v = *(const float4*)(x + (size_t)(b0 + b) * Dn + d0 + c4);
        sx[(c4 + 0) * 520 + b] = v.x;
        sx[(c4 + 1) * 520 + b] = v.y;
        sx[(c4 + 2) * 520 + b] = v.z;
        sx[(c4 + 3) * 520 + b] = v.w;
    }
    __syncthreads();

    // eval: warp w -> d rows 2w (even, low bits) and 2w+1 (odd, high bits)
    const int dA = w << 1, dB = dA + 1;
    const float*  ttA = sT + (dA << 6);
    const float*  ttB = sT + (dB << 6);
    const float2* scA = sSC + dA * 65;
    const float2* scB = sSC + dB * 65;
    u32 packH[16], packL[16];
    #pragma unroll
    for (int ch = 0; ch < 16; ++ch) {
        const int b = (ch << 5) + lane;
        const float xa = sx[dA * 520 + b];
        const float xb = sx[dB * 520 + b];
        int p = 0;
        p += (ttA[31]     <= xa) ? 32 : 0;
        p += (ttA[p + 15] <= xa) ? 16 : 0;
        p += (ttA[p + 7]  <= xa) ? 8  : 0;
        p += (ttA[p + 3]  <= xa) ? 4  : 0;
        p += (ttA[p + 1]  <= xa) ? 2  : 0;
        p += (ttA[p]      <= xa) ? 1  : 0;
        p += (ttA[p]      <= xa) ? 1  : 0;
        int r = 0;
        r += (ttB[31]     <= xb) ? 32 : 0;
        r += (ttB[r + 15] <= xb) ? 16 : 0;
        r += (ttB[r + 7]  <= xb) ? 8  : 0;
        r += (ttB[r + 3]  <= xb) ? 4  : 0;
        r += (ttB[r + 1]  <= xb) ? 2  : 0;
        r += (ttB[r]      <= xb) ? 1  : 0;
        r += (ttB[r]      <= xb) ? 1  : 0;
        const float2 sa = scA[p];
        const float2 sb2 = scB[r];
        const float va = fmaf(sa.x, xa, sa.y);
        const float vb = fmaf(sb2.x, xb, sb2.y);
        u16 hA, lA, hB, lB;
        bsplit(va, hA, lA);
        bsplit(vb, hB, lB);
        packH[ch] = ((u32)hB << 16) | hA;
        packL[ch] = ((u32)lB << 16) | lA;
    }
    __syncthreads();   // sx dead -> reuse as staging

    #pragma unroll
    for (int ch = 0; ch < 16; ++ch) {
        const int b = (ch << 5) + lane;
        stgH[b * 9 + w] = packH[ch];
        stgL[b * 9 + w] = packL[ch];
    }
    __syncthreads();

    // coalesced store: per b, 8 u32 (32B) hi + lo
    const int d0h = blockIdx.y << 3;
    for (int k = t; k < 1024; k += 256) {
        const int b = k >> 1, c4 = (k & 1) << 2;
        const u32* ph = stgH + b * 9 + c4;
        const u32* pl = stgL + b * 9 + c4;
        *(uint4*)(g_Ah + (size_t)(b0 + b) * 128 + d0h + c4) =
            make_uint4(ph[0], ph[1], ph[2], ph[3]);
        *(uint4*)(g_Al + (size_t)(b0 + b) * 128 + d0h + c4) =
            make_uint4(pl[0], pl[1], pl[2], pl[3]);
    }
}

// ---------------------------------------------------------------------------
// kan_mma (identical to R11): 256 threads, GEMM1 4m x 2n warps, g via smem,
// GEMM2 n128 per warp-half. bf16 hi/lo error-corrected.
// ---------------------------------------------------------------------------
#define OF_B1H 0
#define OF_B1L 33792
#define OF_AH  67584
#define OF_AL  101376
#define OF_B2H 135168
#define OF_B2L 172032
#define OF_SB1 208896
#define OF_SB2 209152
#define MMA_SMEM 210176
#define OF_GH 0
#define OF_GL 9216

__global__ __launch_bounds__(256, 1) void kan_mma(
    const float* __restrict__ wo1, const float* __restrict__ bo1,
    const float* __restrict__ wo2, const float* __restrict__ bo2,
    float* __restrict__ out)
{
    extern __shared__ char smc[];
    const u32 sb = smem_u32(smc);
    const int t = threadIdx.x;
    const int b0 = blockIdx.x << 6;

    for (int idx = t; idx < 4096; idx += 256) {
        const int n = idx >> 6, k4 = (idx & 63) << 2;
        const float4 v = *(const float4*)(wo1 + (n << 8) + k4);
        u16 h[4], l[4];
        bsplit(v.x, h[0], l[0]); bsplit(v.y, h[1], l[1]);
        bsplit(v.z, h[2], l[2]); bsplit(v.w, h[3], l[3]);
        *(ushort4*)(smc + OF_B1H + n * 528 + (k4 << 1)) = make_ushort4(h[0], h[1], h[2], h[3]);
        *(ushort4*)(smc + OF_B1L + n * 528 + (k4 << 1)) = make_ushort4(l[0], l[1], l[2], l[3]);
    }
    for (int idx = t; idx < 4096; idx += 256) {
        const int o = idx >> 4, i4 = (idx & 15) << 2;
        const float4 v = *(const float4*)(wo2 + (o << 6) + i4);
        u16 h[4], l[4];
        bsplit(v.x, h[0], l[0]); bsplit(v.y, h[1], l[1]);
        bsplit(v.z, h[2], l[2]); bsplit(v.w, h[3], l[3]);
        *(ushort4*)(smc + OF_B2H + o * 144 + (i4 << 1)) = make_ushort4(h[0], h[1], h[2], h[3]);
        *(ushort4*)(smc + OF_B2L + o * 144 + (i4 << 1)) = make_ushort4(l[0], l[1], l[2], l[3]);
    }
    for (int idx = t; idx < 2048; idx += 256) {
        const int b = idx >> 5, c4 = (idx & 31) << 2;
        *(uint4*)(smc + OF_AH + b * 528 + (c4 << 2)) =
            *(const uint4*)(g_Ah + (size_t)(b0 + b) * 128 + c4);
        *(uint4*)(smc + OF_AL + b * 528 + (c4 << 2)) =
            *(const uint4*)(g_Al + (size_t)(b0 + b) * 128 + c4);
    }
    {
        float* sb1 = (float*)(smc + OF_SB1);
        float* sb2 = (float*)(smc + OF_SB2);
        if (t < 64) sb1[t] = __ldg(bo1 + t);
        if (t < 128) {
            sb2[t] = __ldg(bo2 + t);
            sb2[t + 128] = __ldg(bo2 + t + 128);
        }
    }
    __syncthreads();

    const int w = t >> 5, lane = t & 31;
    const int mrow = (w & 3) << 4;
    const int nh = w >> 2;
    const int q = lane >> 3, rr = lane & 7;
    const int tq = lane & 3, gg = lane >> 2;
    const int b_rowq = (q >> 1) << 3;
    const int b_colq = (q & 1) << 3;

    const u32 aAh = sb + OF_AH + (mrow + rr + ((q & 1) << 3)) * 528 + (((q >> 1) << 3) << 1);
    const u32 aAl = aAh + (OF_AL - OF_AH);

    float D1[4][4];
    #pragma unroll
    for (int nt = 0; nt < 4; ++nt)
        #pragma unroll
        for (int r = 0; r < 4; ++r) D1[nt][r] = 0.f;

    const int np0 = nh << 1;
    #pragma unroll 4
    for (int kt = 0; kt < 16; ++kt) {
        u32 ah[4], al[4];
        ldm4(ah, aAh + (kt << 5));
        ldm4(al, aAl + (kt << 5));
        const u32 bb = sb + OF_B1H + (kt << 5) + (b_colq << 1);
        const int r0 = (np0 << 4) + rr + b_rowq;
        u32 bh0[4], bh1[4], bl0[4];
        ldm4(bh0, bb + r0 * 528);
        ldm4(bh1, bb + (r0 + 16) * 528);
        ldm4(bl0, bb + 33792 + r0 * 528);
        u32 bl1[4];
        ldm4(bl1, bb + 33792 + (r0 + 16) * 528);
        mma_bf16(D1[0], ah, bh0[0], bh0[1]);
        mma_bf16(D1[1], ah, bh0[2], bh0[3]);
        mma_bf16(D1[2], ah, bh1[0], bh1[1]);
        mma_bf16(D1[3], ah, bh1[2], bh1[3]);
        mma_bf16(D1[0], al, bh0[0], bh0[1]);
        mma_bf16(D1[1], al, bh0[2], bh0[3]);
        mma_bf16(D1[2], al, bh1[0], bh1[1]);
        mma_bf16(D1[3], al, bh1[2], bh1[3]);
        mma_bf16(D1[0], ah, bl0[0], bl0[1]);
        mma_bf16(D1[1], ah, bl0[2], bl0[3]);
        mma_bf16(D1[2], ah, bl1[0], bl1[1]);
        mma_bf16(D1[3], ah, bl1[2], bl1[3]);
    }

    u32 ghw[4][2], glw[4][2];
    {
        const float* sb1f = (const float*)(smc + OF_SB1);
        #pragma unroll
        for (int nt = 0; nt < 4; ++nt) {
            const int col = (nh << 5) + (nt << 3) + (tq << 1);
            const float bv0 = sb1f[col], bv1 = sb1f[col + 1];
            const float v0 = fmaxf(D1[nt][0] + bv0, 0.f);
            const float v1 = fmaxf(D1[nt][1] + bv1, 0.f);
            const float v2 = fmaxf(D1[nt][2] + bv0, 0.f);
            const float v3 = fmaxf(D1[nt][3] + bv1, 0.f);
            u16 h0, l0, h1, l1, h2, l2, h3, l3;
            bsplit(v0, h0, l0); bsplit(v1, h1, l1);
            bsplit(v2, h2, l2); bsplit(v3, h3, l3);
            ghw[nt][0] = (u32)h0 | ((u32)h1 << 16);
            ghw[nt][1] = (u32)h2 | ((u32)h3 << 16);
            glw[nt][0] = (u32)l0 | ((u32)l1 << 16);
            glw[nt][1] = (u32)l2 | ((u32)l3 << 16);
        }
    }
    __syncthreads();

    #pragma unroll
    for (int nt = 0; nt < 4; ++nt) {
        const int c2 = ((nh << 5) + (nt << 3) + (tq << 1)) << 1;
        *(u32*)(smc + OF_GH + (mrow + gg) * 144 + c2)     = ghw[nt][0];
        *(u32*)(smc + OF_GH + (mrow + gg + 8) * 144 + c2) = ghw[nt][1];
        *(u32*)(smc + OF_GL + (mrow + gg) * 144 + c2)     = glw[nt][0];
        *(u32*)(smc + OF_GL + (mrow + gg + 8) * 144 + c2) = glw[nt][1];
    }
    __syncthreads();

    float D2[16][4];
    #pragma unroll
    for (int nt = 0; nt < 16; ++nt)
        #pragma unroll
        for (int r = 0; r < 4; ++r) D2[nt][r] = 0.f;

    const u32 gA = sb + OF_GH + (mrow + rr + ((q & 1) << 3)) * 144;
    #pragma unroll
    for (int j = 0; j < 4; ++j) {
        u32 a2h[4], a2l[4];
        const u32 ga = gA + (((j << 4) + ((q >> 1) << 3)) << 1);
        ldm4(a2h, ga);
        ldm4(a2l, ga + (OF_GL - OF_GH));
        #pragma unroll
        for (int pp = 0; pp < 4; ++pp) {
            const int p2 = pp << 1;
            const u32 bb = sb + OF_B2H + (j << 5) + (b_colq << 1);
            const int r0 = (nh << 7) + (p2 << 4) + rr + b_rowq;
            u32 bh0[4], bh1[4], bl0[4], bl1[4];
            ldm4(bh0, bb + r0 * 144);
            ldm4(bh1, bb + (r0 + 16) * 144);
            ldm4(bl0, bb + 36864 + r0 * 144);
            ldm4(bl1, bb + 36864 + (r0 + 16) * 144);
            float* d0 = D2[(p2 << 1) + 0];
            float* d1 = D2[(p2 << 1) + 1];
            float* d2 = D2[(p2 << 1) + 2];
            float* d3 = D2[(p2 << 1) + 3];
            mma_bf16(d0, a2h, bh0[0], bh0[1]);
            mma_bf16(d1, a2h, bh0[2], bh0[3]);
            mma_bf16(d2, a2h, bh1[0], bh1[1]);
            mma_bf16(d3, a2h, bh1[2], bh1[3]);
            mma_bf16(d0, a2l, bh0[0], bh0[1]);
            mma_bf16(d1, a2l, bh0[2], bh0[3]);
            mma_bf16(d2, a2l, bh1[0], bh1[1]);
            mma_bf16(d3, a2l, bh1[2], bh1[3]);
            mma_bf16(d0, a2h, bl0[0], bl0[1]);
            mma_bf16(d1, a2h, bl0[2], bl0[3]);
            mma_bf16(d2, a2h, bl1[0], bl1[1]);
            mma_bf16(d3, a2h, bl1[2], bl1[3]);
        }
    }

    {
        const float* sb2f = (const float*)(smc + OF_SB2);
        #pragma unroll
        for (int nt = 0; nt < 16; ++nt) {
            const int ob = (nh << 7) + (nt << 3);
            const float bv0 = sb2f[ob + (tq << 1)];
            const float bv1 = sb2f[ob + (tq << 1) + 1];
            const int row = b0 + mrow + gg;
            *(float2*)(out + (size_t)row * ONn + ob + (tq << 1)) =
                make_float2(D2[nt][0] + bv0, D2[nt][1] + bv1);
            *(float2*)(out + (size_t)(row + 8) * ONn + ob + (tq << 1)) =
                make_float2(D2[nt][2] + bv0, D2[nt][3] + bv1);
        }
    }
}

// ---------------------------------------------------------------------------
extern "C" void kernel_launch(void* const* d_in, const int* in_sizes, int n_in,
                              void* d_out, int out_size)
{
    const float* x   = (const float*)d_in[0];
    const float* w1  = (const float*)d_in[1];
    const float* b1  = (const float*)d_in[2];
    const float* w2  = (const float*)d_in[3];
    const float* b2  = (const float*)d_in[4];
    const float* wo1 = (const float*)d_in[5];
    const float* bo1 = (const float*)d_in[6];
    const float* wo2 = (const float*)d_in[7];
    const float* bo2 = (const float*)d_in[8];
    float* out = (float*)d_out;

    cudaFuncSetAttribute(kan_eval, cudaFuncAttributeMaxDynamicSharedMemorySize, EVAL_SMEM);
    cudaFuncSetAttribute(kan_mma,  cudaFuncAttributeMaxDynamicSharedMemorySize, MMA_SMEM);

    kan_eval<<<dim3(Bn / 512, Dn / 16), 256, EVAL_SMEM>>>(x, w1, b1, w2, b2);
    kan_mma<<<Bn / 64, 256, MMA_SMEM>>>(wo1, bo1, wo2, bo2, out);
}

// round 13
// speedup vs baseline: 1.1404x; 1.1404x over previous
#include <cuda_runtime.h>
#include <cuda_bf16.h>
#include <cstdint>

#define Bn 8192
#define Dn 256
#define INn 64
#define ONn 256

typedef unsigned int u32;
typedef unsigned short u16;

// A matrix (inner acts) as packed bf16 pairs: [b][d/2], low half = even d
__device__ __align__(16) u32 g_Ah[(size_t)Bn * (Dn / 2)];   // 4MB
__device__ __align__(16) u32 g_Al[(size_t)Bn * (Dn / 2)];   // 4MB
// pre-converted bf16 hi/lo weight images (row-major, written by eval x==0 blocks)
__device__ __align__(16) u16 g_W1h[64 * 256];
__device__ __align__(16) u16 g_W1l[64 * 256];
__device__ __align__(16) u16 g_W2h[256 * 64];
__device__ __align__(16) u16 g_W2l[256 * 64];

__device__ __forceinline__ u32 smem_u32(const void* p) {
    u32 a;
    asm("{ .reg .u64 t; cvta.to.shared.u64 t, %1; cvt.u32.u64 %0, t; }" : "=r"(a) : "l"(p));
    return a;
}
__device__ __forceinline__ void ldm4(u32* r, u32 addr) {
    asm volatile("ldmatrix.sync.aligned.m8n8.x4.shared.b16 {%0,%1,%2,%3}, [%4];"
                 : "=r"(r[0]), "=r"(r[1]), "=r"(r[2]), "=r"(r[3]) : "r"(addr));
}
__device__ __forceinline__ void mma_bf16(float* d, const u32* a, u32 b0, u32 b1) {
    asm volatile("mma.sync.aligned.m16n8k16.row.col.f32.bf16.bf16.f32 "
                 "{%0,%1,%2,%3}, {%4,%5,%6,%7}, {%8,%9}, {%0,%1,%2,%3};"
                 : "+f"(d[0]), "+f"(d[1]), "+f"(d[2]), "+f"(d[3])
                 : "r"(a[0]), "r"(a[1]), "r"(a[2]), "r"(a[3]), "r"(b0), "r"(b1));
}
__device__ __forceinline__ void bsplit(float v, u16& h, u16& l) {
    __nv_bfloat16 hb = __float2bfloat16(v);
    h = __bfloat16_as_ushort(hb);
    l = __bfloat16_as_ushort(__float2bfloat16(v - __bfloat162float(hb)));
}

// ---------------------------------------------------------------------------
// kan_eval (prep fused, R12-verified) + weight image conversion on x==0 blocks
// ---------------------------------------------------------------------------
#define R2OFF 3104
#define EVAL_SMEM ((R2OFF + 9216) * 4)   // 49280 bytes

__global__ __launch_bounds__(256, 2) void kan_eval(
    const float* __restrict__ x,
    const float* __restrict__ w1, const float* __restrict__ b1,
    const float* __restrict__ w2, const float* __restrict__ b2,
    const float* __restrict__ wo1, const float* __restrict__ wo2)
{
    extern __shared__ float sm[];
    float*  sT  = sm;                        // [16][64] sorted breakpoints
    float2* sSC = (float2*)(sm + 1024);      // [16][65] segment (S,C)
    float*  r2  = sm + R2OFF;
    float* skey = r2;                        // [16][65]
    float* ssK  = r2 + 3120;                 // [16][65] sorted
    float* ssS  = r2 + 4160;
    float* ssC  = r2 + 5200;
    float* sx   = r2;                        // [16][520]
    u32*  stgH  = (u32*)r2;                  // [512][9]
    u32*  stgL  = (u32*)r2 + 4608;

    const int t = threadIdx.x;
    const int lane = t & 31, w = t >> 5;
    const int b0 = blockIdx.x << 9;
    const int d0 = blockIdx.y << 4;

    // ---- weight image conversion (16 blocks do 1/16 each)
    if (blockIdx.x == 0) {
        const int base = (blockIdx.y << 10) + (t << 2);
        {
            const float4 v = *(const float4*)(wo1 + base);
            u16 h[4], l[4];
            bsplit(v.x, h[0], l[0]); bsplit(v.y, h[1], l[1]);
            bsplit(v.z, h[2], l[2]); bsplit(v.w, h[3], l[3]);
            *(ushort4*)(g_W1h + base) = make_ushort4(h[0], h[1], h[2], h[3]);
            *(ushort4*)(g_W1l + base) = make_ushort4(l[0], l[1], l[2], l[3]);
        }
        {
            const float4 v = *(const float4*)(wo2 + base);
            u16 h[4], l[4];
            bsplit(v.x, h[0], l[0]); bsplit(v.y, h[1], l[1]);
            bsplit(v.z, h[2], l[2]); bsplit(v.w, h[3], l[3]);
            *(ushort4*)(g_W2h + base) = make_ushort4(h[0], h[1], h[2], h[3]);
            *(ushort4*)(g_W2l + base) = make_ushort4(l[0], l[1], l[2], l[3]);
        }
    }

    // ---------------- Phase P: LUT build ----------------
    const int dl = t >> 4;
    const int i0 = (t & 15) << 2;
    float key[4], dS[4], dC[4];
    float myBS = 0.f, myBC = 0.f;
    {
        const int base = (d0 + dl) * INn + i0;
        const float4 w4 = *(const float4*)(w1 + base);
        const float4 b4 = *(const float4*)(b1 + base);
        const float4 v4 = *(const float4*)(w2 + base);
        const float* wf = (const float*)&w4;
        const float* bf = (const float*)&b4;
        const float* vf = (const float*)&v4;
        #pragma unroll
        for (int q = 0; q < 4; ++q) {
            const float ww = wf[q], bb = bf[q], vv = vf[q];
            if (ww == 0.f) {
                key[q] = __int_as_float(0x7f800000);
                dS[q] = 0.f; dC[q] = 0.f;
                myBC += fmaxf(bb, 0.f) * vv;
            } else {
                key[q] = -bb / ww;
                const float pS = ww * vv, pC = bb * vv;
                if (ww > 0.f) { dS[q] = pS;  dC[q] = pC; }
                else          { dS[q] = -pS; dC[q] = -pC; myBS += pS; myBC += pC; }
            }
            skey[dl * 65 + i0 + q] = key[q];
        }
    }
    #pragma unroll
    for (int off = 8; off >= 1; off >>= 1) {
        myBS += __shfl_xor_sync(~0u, myBS, off);
        myBC += __shfl_xor_sync(~0u, myBC, off);
    }
    __syncthreads();

    #pragma unroll
    for (int q = 0; q < 4; ++q) {
        const float kq = key[q];
        const int iq = i0 + q;
        int rank = 0;
        const float* row = skey + dl * 65;
        #pragma unroll
        for (int j = 0; j < 64; ++j) {
            const float tj = row[j];
            rank += (tj < kq || (tj == kq && j < iq)) ? 1 : 0;
        }
        ssK[dl * 65 + rank] = kq;
        ssS[dl * 65 + rank] = dS[q];
        ssC[dl * 65 + rank] = dC[q];
    }
    __syncthreads();

    #pragma unroll
    for (int h = 0; h < 2; ++h) {
        const int dd = (w << 1) + h;
        float s0 = ssS[dd * 65 + lane], s1 = ssS[dd * 65 + lane + 32];
        float c0 = ssC[dd * 65 + lane], c1 = ssC[dd * 65 + lane + 32];
        #pragma unroll
        for (int off = 1; off < 32; off <<= 1) {
            const float a0 = __shfl_up_sync(~0u, s0, off);
            const float a1 = __shfl_up_sync(~0u, c0, off);
            const float a2 = __shfl_up_sync(~0u, s1, off);
            const float a3 = __shfl_up_sync(~0u, c1, off);
            if (lane >= off) { s0 += a0; c0 += a1; s1 += a2; c1 += a3; }
        }
        s1 += __shfl_sync(~0u, s0, 31);
        c1 += __shfl_sync(~0u, c0, 31);
        float bS = __shfl_sync(~0u, myBS, h << 4);
        float bC = __shfl_sync(~0u, myBC, h << 4);
        bC += __ldg(b2 + d0 + dd);
        sT[(dd << 6) + lane]      = ssK[dd * 65 + lane];
        sT[(dd << 6) + lane + 32] = ssK[dd * 65 + lane + 32];
        if (lane == 0) sSC[dd * 65] = make_float2(bS, bC);
        sSC[dd * 65 + 1 + lane]  = make_float2(bS + s0, bC + c0);
        sSC[dd * 65 + 33 + lane] = make_float2(bS + s1, bC + c1);
    }
    __syncthreads();

    // ---------------- Phase E ----------------
    for (int k = t; k < 2048; k += 256) {
        const int b = k >> 2, c4 = (k & 3) << 2;
        const float4 v = *(const float4*)(x + (size_t)(b0 + b) * Dn + d0 + c4);
        sx[(c4 + 0) * 520 + b] = v.x;
        sx[(c4 + 1) * 520 + b] = v.y;
        sx[(c4 + 2) * 520 + b] = v.z;
        sx[(c4 + 3) * 520 + b] = v.w;
    }
    __syncthreads();

    const int dA = w << 1, dB = dA + 1;
    const float*  ttA = sT + (dA << 6);
    const float*  ttB = sT + (dB << 6);
    const float2* scA = sSC + dA * 65;
    const float2* scB = sSC + dB * 65;
    u32 packH[16], packL[16];
    #pragma unroll
    for (int ch = 0; ch < 16; ++ch) {
        const int b = (ch << 5) + lane;
        const float xa = sx[dA * 520 + b];
        const float xb = sx[dB * 520 + b];
        int p = 0;
        p += (ttA[31]     <= xa) ? 32 : 0;
        p += (ttA[p + 15] <= xa) ? 16 : 0;
        p += (ttA[p + 7]  <= xa) ? 8  : 0;
        p += (ttA[p + 3]  <= xa) ? 4  : 0;
        p += (ttA[p + 1]  <= xa) ? 2  : 0;
        p += (ttA[p]      <= xa) ? 1  : 0;
        p += (ttA[p]      <= xa) ? 1  : 0;
        int r = 0;
        r += (ttB[31]     <= xb) ? 32 : 0;
        r += (ttB[r + 15] <= xb) ? 16 : 0;
        r += (ttB[r + 7]  <= xb) ? 8  : 0;
        r += (ttB[r + 3]  <= xb) ? 4  : 0;
        r += (ttB[r + 1]  <= xb) ? 2  : 0;
        r += (ttB[r]      <= xb) ? 1  : 0;
        r += (ttB[r]      <= xb) ? 1  : 0;
        const float2 sa = scA[p];
        const float2 sb2 = scB[r];
        const float va = fmaf(sa.x, xa, sa.y);
        const float vb = fmaf(sb2.x, xb, sb2.y);
        u16 hA, lA, hB, lB;
        bsplit(va, hA, lA);
        bsplit(vb, hB, lB);
        packH[ch] = ((u32)hB << 16) | hA;
        packL[ch] = ((u32)lB << 16) | lA;
    }
    __syncthreads();

    #pragma unroll
    for (int ch = 0; ch < 16; ++ch) {
        const int b = (ch << 5) + lane;
        stgH[b * 9 + w] = packH[ch];
        stgL[b * 9 + w] = packL[ch];
    }
    __syncthreads();

    const int d0h = blockIdx.y << 3;
    for (int k = t; k < 1024; k += 256) {
        const int b = k >> 1, c4 = (k & 1) << 2;
        const u32* ph = stgH + b * 9 + c4;
        const u32* pl = stgL + b * 9 + c4;
        *(uint4*)(g_Ah + (size_t)(b0 + b) * 128 + d0h + c4) =
            make_uint4(ph[0], ph[1], ph[2], ph[3]);
        *(uint4*)(g_Al + (size_t)(b0 + b) * 128 + d0h + c4) =
            make_uint4(pl[0], pl[1], pl[2], pl[3]);
    }
}

// ---------------------------------------------------------------------------
// kan_mma v3: btile 32, grid 256, 256 threads, smem ~100KB -> occ 2.
// Pure-copy loads (weights pre-converted). Phase2 region aliases phase1.
// GEMM1: 2 m-warps x 4 n-warps (n16/warp). GEMM2: n64/warp, 32 accum regs.
// ---------------------------------------------------------------------------
#define OF_B1H 0
#define OF_B1L 33792
#define OF_AH  67584
#define OF_AL  84480
#define OF_SB1 101376
#define OF_SB2 101632
#define MMA_SMEM 102656
// phase-2 aliases (dead regions after GEMM1)
#define OF_B2H 0
#define OF_B2L 36864
#define OF_GH  73728
#define OF_GL  82944

__global__ __launch_bounds__(256, 2) void kan_mma(
    const float* __restrict__ bo1, const float* __restrict__ bo2,
    float* __restrict__ out)
{
    extern __shared__ char smc[];
    const u32 sb = smem_u32(smc);
    const int t = threadIdx.x;
    const int b0 = blockIdx.x << 5;      // btile 32

    // ---- copy B1 images (pitch 528B) + A tile (pitch 528B) + biases
    for (int idx = t; idx < 2048; idx += 256) {
        const int n = idx >> 5, k8 = (idx & 31) << 3;
        *(uint4*)(smc + OF_B1H + n * 528 + (k8 << 1)) = *(const uint4*)(g_W1h + (n << 8) + k8);
        *(uint4*)(smc + OF_B1L + n * 528 + (k8 << 1)) = *(const uint4*)(g_W1l + (n << 8) + k8);
    }
    for (int idx = t; idx < 1024; idx += 256) {
        const int b = idx >> 5, c4 = (idx & 31) << 2;
        *(uint4*)(smc + OF_AH + b * 528 + (c4 << 2)) =
            *(const uint4*)(g_Ah + (size_t)(b0 + b) * 128 + c4);
        *(uint4*)(smc + OF_AL + b * 528 + (c4 << 2)) =
            *(const uint4*)(g_Al + (size_t)(b0 + b) * 128 + c4);
    }
    {
        float* sb1 = (float*)(smc + OF_SB1);
        float* sb2 = (float*)(smc + OF_SB2);
        if (t < 64) sb1[t] = __ldg(bo1 + t);
        if (t < 128) {
            sb2[t] = __ldg(bo2 + t);
            sb2[t + 128] = __ldg(bo2 + t + 128);
        }
    }
    __syncthreads();

    const int w = t >> 5, lane = t & 31;
    const int mw = w & 1, nw = w >> 1;   // 2 m-warps x 4 n-warps
    const int mrow = mw << 4;
    const int q = lane >> 3, rr = lane & 7;
    const int tq = lane & 3, gg = lane >> 2;
    const int b_rowq = (q >> 1) << 3;
    const int b_colq = (q & 1) << 3;

    const u32 aAh = sb + OF_AH + (mrow + rr + ((q & 1) << 3)) * 528 + (((q >> 1) << 3) << 1);
    const u32 aAl = aAh + (OF_AL - OF_AH);

    // ---- GEMM1: warp = m16 x n16, K=256
    float D1[2][4];
    #pragma unroll
    for (int nt = 0; nt < 2; ++nt)
        #pragma unroll
        for (int r = 0; r < 4; ++r) D1[nt][r] = 0.f;

    const int r0 = (nw << 4) + rr + b_rowq;
    #pragma unroll 4
    for (int kt = 0; kt < 16; ++kt) {
        u32 ah[4], al[4], bh[4], bl[4];
        ldm4(ah, aAh + (kt << 5));
        ldm4(al, aAl + (kt << 5));
        const u32 bb = sb + OF_B1H + (kt << 5) + (b_colq << 1) + r0 * 528;
        ldm4(bh, bb);
        ldm4(bl, bb + (OF_B1L - OF_B1H));
        mma_bf16(D1[0], ah, bh[0], bh[1]);
        mma_bf16(D1[1], ah, bh[2], bh[3]);
        mma_bf16(D1[0], al, bh[0], bh[1]);
        mma_bf16(D1[1], al, bh[2], bh[3]);
        mma_bf16(D1[0], ah, bl[0], bl[1]);
        mma_bf16(D1[1], ah, bl[2], bl[3]);
    }

    // ---- epilogue 1: relu(D1 + bo1) -> packed g words in registers
    u32 ghw[2][2], glw[2][2];
    {
        const float* sb1f = (const float*)(smc + OF_SB1);
        #pragma unroll
        for (int nt = 0; nt < 2; ++nt) {
            const int col = (nw << 4) + (nt << 3) + (tq << 1);
            const float bv0 = sb1f[col], bv1 = sb1f[col + 1];
            const float v0 = fmaxf(D1[nt][0] + bv0, 0.f);
            const float v1 = fmaxf(D1[nt][1] + bv1, 0.f);
            const float v2 = fmaxf(D1[nt][2] + bv0, 0.f);
            const float v3 = fmaxf(D1[nt][3] + bv1, 0.f);
            u16 h0, l0, h1, l1, h2, l2, h3, l3;
            bsplit(v0, h0, l0); bsplit(v1, h1, l1);
            bsplit(v2, h2, l2); bsplit(v3, h3, l3);
            ghw[nt][0] = (u32)h0 | ((u32)h1 << 16);
            ghw[nt][1] = (u32)h2 | ((u32)h3 << 16);
            glw[nt][0] = (u32)l0 | ((u32)l1 << 16);
            glw[nt][1] = (u32)l2 | ((u32)l3 << 16);
        }
    }
    __syncthreads();   // phase-1 smem dead

    // ---- write g (pitch 144B) + copy B2 images (pitch 144B)
    #pragma unroll
    for (int nt = 0; nt < 2; ++nt) {
        const int c2 = ((nw << 4) + (nt << 3) + (tq << 1)) << 1;
        *(u32*)(smc + OF_GH + (mrow + gg) * 144 + c2)     = ghw[nt][0];
        *(u32*)(smc + OF_GH + (mrow + gg + 8) * 144 + c2) = ghw[nt][1];
        *(u32*)(smc + OF_GL + (mrow + gg) * 144 + c2)     = glw[nt][0];
        *(u32*)(smc + OF_GL + (mrow + gg + 8) * 144 + c2) = glw[nt][1];
    }
    for (int idx = t; idx < 2048; idx += 256) {
        const int o = idx >> 3, i8 = (idx & 7) << 3;
        *(uint4*)(smc + OF_B2H + o * 144 + (i8 << 1)) = *(const uint4*)(g_W2h + (o << 6) + i8);
        *(uint4*)(smc + OF_B2L + o * 144 + (i8 << 1)) = *(const uint4*)(g_W2l + (o << 6) + i8);
    }
    __syncthreads();

    // ---- GEMM2: warp = m16 x n64 (8 ntiles), K=64
    float D2[8][4];
    #pragma unroll
    for (int nt = 0; nt < 8; ++nt)
        #pragma unroll
        for (int r = 0; r < 4; ++r) D2[nt][r] = 0.f;

    const u32 gA = sb + OF_GH + (mrow + rr + ((q & 1) << 3)) * 144;
    #pragma unroll
    for (int j = 0; j < 4; ++j) {
        u32 a2h[4], a2l[4];
        const u32 ga = gA + (((j << 4) + ((q >> 1) << 3)) << 1);
        ldm4(a2h, ga);
        ldm4(a2l, ga + (OF_GL - OF_GH));
        #pragma unroll
        for (int cp = 0; cp < 2; ++cp) {
            // two n16 chunks per pass -> 12 mma over 4 accumulators (RAW dist 4)
            const int c0r = (nw << 6) + ((cp << 1) << 4) + rr + b_rowq;
            const u32 bb = sb + OF_B2H + (j << 5) + (b_colq << 1);
            u32 bh0[4], bl0[4], bh1[4], bl1[4];
            ldm4(bh0, bb + c0r * 144);
            ldm4(bl0, bb + (OF_B2L - OF_B2H) + c0r * 144);
            ldm4(bh1, bb + (c0r + 16) * 144);
            ldm4(bl1, bb + (OF_B2L - OF_B2H) + (c0r + 16) * 144);
            float* d0 = D2[(cp << 2) + 0];
            float* d1 = D2[(cp << 2) + 1];
            float* d2 = D2[(cp << 2) + 2];
            float* d3 = D2[(cp << 2) + 3];
            mma_bf16(d0, a2h, bh0[0], bh0[1]);
            mma_bf16(d1, a2h, bh0[2], bh0[3]);
            mma_bf16(d2, a2h, bh1[0], bh1[1]);
            mma_bf16(d3, a2h, bh1[2], bh1[3]);
            mma_bf16(d0, a2l, bh0[0], bh0[1]);
            mma_bf16(d1, a2l, bh0[2], bh0[3]);
            mma_bf16(d2, a2l, bh1[0], bh1[1]);
            mma_bf16(d3, a2l, bh1[2], bh1[3]);
            mma_bf16(d0, a2h, bl0[0], bl0[1]);
            mma_bf16(d1, a2h, bl0[2], bl0[3]);
            mma_bf16(d2, a2h, bl1[0], bl1[1]);
            mma_bf16(d3, a2h, bl1[2], bl1[3]);
        }
    }

    // ---- store out + bo2
    {
        const float* sb2f = (const float*)(smc + OF_SB2);
        #pragma unroll
        for (int nt = 0; nt < 8; ++nt) {
            const int ob = (nw << 6) + (nt << 3);
            const float bv0 = sb2f[ob + (tq << 1)];
            const float bv1 = sb2f[ob + (tq << 1) + 1];
            const int row = b0 + mrow + gg;
            *(float2*)(out + (size_t)row * ONn + ob + (tq << 1)) =
                make_float2(D2[nt][0] + bv0, D2[nt][1] + bv1);
            *(float2*)(out + (size_t)(row + 8) * ONn + ob + (tq << 1)) =
                make_float2(D2[nt][2] + bv0, D2[nt][3] + bv1);
        }
    }
}

// ---------------------------------------------------------------------------
extern "C" void kernel_launch(void* const* d_in, const int* in_sizes, int n_in,
                              void* d_out, int out_size)
{
    const float* x   = (const float*)d_in[0];
    const float* w1  = (const float*)d_in[1];
    const float* b1  = (const float*)d_in[2];
    const float* w2  = (const float*)d_in[3];
    const float* b2  = (const float*)d_in[4];
    const float* wo1 = (const float*)d_in[5];
    const float* bo1 = (const float*)d_in[6];
    const float* wo2 = (const float*)d_in[7];
    const float* bo2 = (const float*)d_in[8];
    float* out = (float*)d_out;

    cudaFuncSetAttribute(kan_eval, cudaFuncAttributeMaxDynamicSharedMemorySize, EVAL_SMEM);
    cudaFuncSetAttribute(kan_mma,  cudaFuncAttributeMaxDynamicSharedMemorySize, MMA_SMEM);

    kan_eval<<<dim3(Bn / 512, Dn / 16), 256, EVAL_SMEM>>>(x, w1, b1, w2, b2, wo1, wo2);
    kan_mma<<<Bn / 32, 256, MMA_SMEM>>>(bo1, bo2, out);
}

// round 14
// speedup vs baseline: 1.2366x; 1.0844x over previous
#include <cuda_runtime.h>
#include <cuda_fp16.h>
#include <cstdint>

#define Bn 8192
#define Dn 256
#define INn 64
#define ONn 256

typedef unsigned int u32;
typedef unsigned short u16;

// A matrix (inner acts) as packed fp16 pairs: [b][d/2], low half = even d
__device__ __align__(16) u32 g_A[(size_t)Bn * (Dn / 2)];    // 4MB
// pre-converted fp16 weight images (row-major, written by eval x==0 blocks)
__device__ __align__(16) u16 g_W1[64 * 256];
__device__ __align__(16) u16 g_W2[256 * 64];

__device__ __forceinline__ u32 smem_u32(const void* p) {
    u32 a;
    asm("{ .reg .u64 t; cvta.to.shared.u64 t, %1; cvt.u32.u64 %0, t; }" : "=r"(a) : "l"(p));
    return a;
}
__device__ __forceinline__ void ldm4(u32* r, u32 addr) {
    asm volatile("ldmatrix.sync.aligned.m8n8.x4.shared.b16 {%0,%1,%2,%3}, [%4];"
                 : "=r"(r[0]), "=r"(r[1]), "=r"(r[2]), "=r"(r[3]) : "r"(addr));
}
__device__ __forceinline__ void mma_f16(float* d, const u32* a, u32 b0, u32 b1) {
    asm volatile("mma.sync.aligned.m16n8k16.row.col.f32.f16.f16.f32 "
                 "{%0,%1,%2,%3}, {%4,%5,%6,%7}, {%8,%9}, {%0,%1,%2,%3};"
                 : "+f"(d[0]), "+f"(d[1]), "+f"(d[2]), "+f"(d[3])
                 : "r"(a[0]), "r"(a[1]), "r"(a[2]), "r"(a[3]), "r"(b0), "r"(b1));
}
__device__ __forceinline__ u16 f2h(float v) {
    return __half_as_ushort(__float2half(v));
}

// ---------------------------------------------------------------------------
// kan_eval (prep fused) + fp16 weight image conversion on x==0 blocks.
// grid (B/512, D/16), 256 threads, occ 2.
// ---------------------------------------------------------------------------
#define R2OFF 3104
#define EVAL_SMEM ((R2OFF + 8320) * 4)

__global__ __launch_bounds__(256, 2) void kan_eval(
    const float* __restrict__ x,
    const float* __restrict__ w1, const float* __restrict__ b1,
    const float* __restrict__ w2, const float* __restrict__ b2,
    const float* __restrict__ wo1, const float* __restrict__ wo2)
{
    extern __shared__ float sm[];
    float*  sT  = sm;                        // [16][64] sorted breakpoints
    float2* sSC = (float2*)(sm + 1024);      // [16][65] segment (S,C)
    float*  r2  = sm + R2OFF;
    float* skey = r2;                        // [16][65]
    float* ssK  = r2 + 3120;
    float* ssS  = r2 + 4160;
    float* ssC  = r2 + 5200;
    float* sx   = r2;                        // [16][520]
    u32*  stgA  = (u32*)r2;                  // [512][9]

    const int t = threadIdx.x;
    const int lane = t & 31, w = t >> 5;
    const int b0 = blockIdx.x << 9;
    const int d0 = blockIdx.y << 4;

    // ---- fp16 weight image conversion (16 blocks do 1/16 each)
    if (blockIdx.x == 0) {
        const int base = (blockIdx.y << 10) + (t << 2);
        {
            const float4 v = *(const float4*)(wo1 + base);
            *(ushort4*)(g_W1 + base) =
                make_ushort4(f2h(v.x), f2h(v.y), f2h(v.z), f2h(v.w));
        }
        {
            const float4 v = *(const float4*)(wo2 + base);
            *(ushort4*)(g_W2 + base) =
                make_ushort4(f2h(v.x), f2h(v.y), f2h(v.z), f2h(v.w));
        }
    }

    // ---------------- Phase P: LUT build (R12-verified) ----------------
    const int dl = t >> 4;
    const int i0 = (t & 15) << 2;
    float key[4], dS[4], dC[4];
    float myBS = 0.f, myBC = 0.f;
    {
        const int base = (d0 + dl) * INn + i0;
        const float4 w4 = *(const float4*)(w1 + base);
        const float4 b4 = *(const float4*)(b1 + base);
        const float4 v4 = *(const float4*)(w2 + base);
        const float* wf = (const float*)&w4;
        const float* bf = (const float*)&b4;
        const float* vf = (const float*)&v4;
        #pragma unroll
        for (int q = 0; q < 4; ++q) {
            const float ww = wf[q], bb = bf[q], vv = vf[q];
            if (ww == 0.f) {
                key[q] = __int_as_float(0x7f800000);
                dS[q] = 0.f; dC[q] = 0.f;
                myBC += fmaxf(bb, 0.f) * vv;
            } else {
                key[q] = -bb / ww;
                const float pS = ww * vv, pC = bb * vv;
                if (ww > 0.f) { dS[q] = pS;  dC[q] = pC; }
                else          { dS[q] = -pS; dC[q] = -pC; myBS += pS; myBC += pC; }
            }
            skey[dl * 65 + i0 + q] = key[q];
        }
    }
    #pragma unroll
    for (int off = 8; off >= 1; off >>= 1) {
        myBS += __shfl_xor_sync(~0u, myBS, off);
        myBC += __shfl_xor_sync(~0u, myBC, off);
    }
    __syncthreads();

    #pragma unroll
    for (int q = 0; q < 4; ++q) {
        const float kq = key[q];
        const int iq = i0 + q;
        int rank = 0;
        const float* row = skey + dl * 65;
        #pragma unroll
        for (int j = 0; j < 64; ++j) {
            const float tj = row[j];
            rank += (tj < kq || (tj == kq && j < iq)) ? 1 : 0;
        }
        ssK[dl * 65 + rank] = kq;
        ssS[dl * 65 + rank] = dS[q];
        ssC[dl * 65 + rank] = dC[q];
    }
    __syncthreads();

    #pragma unroll
    for (int h = 0; h < 2; ++h) {
        const int dd = (w << 1) + h;
        float s0 = ssS[dd * 65 + lane], s1 = ssS[dd * 65 + lane + 32];
        float c0 = ssC[dd * 65 + lane], c1 = ssC[dd * 65 + lane + 32];
        #pragma unroll
        for (int off = 1; off < 32; off <<= 1) {
            const float a0 = __shfl_up_sync(~0u, s0, off);
            const float a1 = __shfl_up_sync(~0u, c0, off);
            const float a2 = __shfl_up_sync(~0u, s1, off);
            const float a3 = __shfl_up_sync(~0u, c1, off);
            if (lane >= off) { s0 += a0; c0 += a1; s1 += a2; c1 += a3; }
        }
        s1 += __shfl_sync(~0u, s0, 31);
        c1 += __shfl_sync(~0u, c0, 31);
        float bS = __shfl_sync(~0u, myBS, h << 4);
        float bC = __shfl_sync(~0u, myBC, h << 4);
        bC += __ldg(b2 + d0 + dd);
        sT[(dd << 6) + lane]      = ssK[dd * 65 + lane];
        sT[(dd << 6) + lane + 32] = ssK[dd * 65 + lane + 32];
        if (lane == 0) sSC[dd * 65] = make_float2(bS, bC);
        sSC[dd * 65 + 1 + lane]  = make_float2(bS + s0, bC + c0);
        sSC[dd * 65 + 33 + lane] = make_float2(bS + s1, bC + c1);
    }
    __syncthreads();

    // ---------------- Phase E ----------------
    for (int k = t; k < 2048; k += 256) {
        const int b = k >> 2, c4 = (k & 3) << 2;
        const float4 v = *(const float4*)(x + (size_t)(b0 + b) * Dn + d0 + c4);
        sx[(c4 + 0) * 520 + b] = v.x;
        sx[(c4 + 1) * 520 + b] = v.y;
        sx[(c4 + 2) * 520 + b] = v.z;
        sx[(c4 + 3) * 520 + b] = v.w;
    }
    __syncthreads();

    const int dA = w << 1, dB = dA + 1;
    const float*  ttA = sT + (dA << 6);
    const float*  ttB = sT + (dB << 6);
    const float2* scA = sSC + dA * 65;
    const float2* scB = sSC + dB * 65;
    u32 packA[16];
    #pragma unroll
    for (int ch = 0; ch < 16; ++ch) {
        const int b = (ch << 5) + lane;
        const float xa = sx[dA * 520 + b];
        const float xb = sx[dB * 520 + b];
        int p = 0;
        p += (ttA[31]     <= xa) ? 32 : 0;
        p += (ttA[p + 15] <= xa) ? 16 : 0;
        p += (ttA[p + 7]  <= xa) ? 8  : 0;
        p += (ttA[p + 3]  <= xa) ? 4  : 0;
        p += (ttA[p + 1]  <= xa) ? 2  : 0;
        p += (ttA[p]      <= xa) ? 1  : 0;
        p += (ttA[p]      <= xa) ? 1  : 0;
        int r = 0;
        r += (ttB[31]     <= xb) ? 32 : 0;
        r += (ttB[r + 15] <= xb) ? 16 : 0;
        r += (ttB[r + 7]  <= xb) ? 8  : 0;
        r += (ttB[r + 3]  <= xb) ? 4  : 0;
        r += (ttB[r + 1]  <= xb) ? 2  : 0;
        r += (ttB[r]      <= xb) ? 1  : 0;
        r += (ttB[r]      <= xb) ? 1  : 0;
        const float2 sa = scA[p];
        const float2 sb2 = scB[r];
        const float va = fmaf(sa.x, xa, sa.y);
        const float vb = fmaf(sb2.x, xb, sb2.y);
        packA[ch] = ((u32)f2h(vb) << 16) | f2h(va);
    }
    __syncthreads();   // sx dead -> staging

    #pragma unroll
    for (int ch = 0; ch < 16; ++ch) {
        const int b = (ch << 5) + lane;
        stgA[b * 9 + w] = packA[ch];
    }
    __syncthreads();

    const int d0h = blockIdx.y << 3;
    for (int k = t; k < 1024; k += 256) {
        const int b = k >> 1, c4 = (k & 1) << 2;
        const u32* pa = stgA + b * 9 + c4;
        *(uint4*)(g_A + (size_t)(b0 + b) * 128 + d0h + c4) =
            make_uint4(pa[0], pa[1], pa[2], pa[3]);
    }
}

// ---------------------------------------------------------------------------
// kan_mma v4: single-pass fp16, ALL operands resident up front (93.4KB, occ 2),
// one sync between GEMM1 epilogue and GEMM2. btile 32, grid 256, 256 threads.
// GEMM1: 2 m-warps x 4 n-warps (n16/warp). GEMM2: n64/warp.
// ---------------------------------------------------------------------------
#define OF_B1  0
#define OF_B2  33792
#define OF_A   70656
#define OF_G   87552
#define OF_SB1 92160
#define OF_SB2 92416
#define MMA_SMEM 93440
// pitches (bytes): B1,A rows = 528; B2,g rows = 144

__global__ __launch_bounds__(256, 2) void kan_mma(
    const float* __restrict__ bo1, const float* __restrict__ bo2,
    float* __restrict__ out)
{
    extern __shared__ char smc[];
    const u32 sb = smem_u32(smc);
    const int t = threadIdx.x;
    const int b0 = blockIdx.x << 5;

    // ---- all loads up front (pure copies, high MLP)
    for (int idx = t; idx < 2048; idx += 256) {
        const int n = idx >> 5, k8 = (idx & 31) << 3;
        *(uint4*)(smc + OF_B1 + n * 528 + (k8 << 1)) = *(const uint4*)(g_W1 + (n << 8) + k8);
    }
    for (int idx = t; idx < 2048; idx += 256) {
        const int o = idx >> 3, i8 = (idx & 7) << 3;
        *(uint4*)(smc + OF_B2 + o * 144 + (i8 << 1)) = *(const uint4*)(g_W2 + (o << 6) + i8);
    }
    for (int idx = t; idx < 1024; idx += 256) {
        const int b = idx >> 5, c4 = (idx & 31) << 2;
        *(uint4*)(smc + OF_A + b * 528 + (c4 << 2)) =
            *(const uint4*)(g_A + (size_t)(b0 + b) * 128 + c4);
    }
    {
        float* sb1 = (float*)(smc + OF_SB1);
        float* sb2 = (float*)(smc + OF_SB2);
        if (t < 64) sb1[t] = __ldg(bo1 + t);
        if (t < 128) {
            sb2[t] = __ldg(bo2 + t);
            sb2[t + 128] = __ldg(bo2 + t + 128);
        }
    }
    __syncthreads();

    const int w = t >> 5, lane = t & 31;
    const int mw = w & 1, nw = w >> 1;
    const int mrow = mw << 4;
    const int q = lane >> 3, rr = lane & 7;
    const int tq = lane & 3, gg = lane >> 2;
    const int b_rowq = (q >> 1) << 3;
    const int b_colq = (q & 1) << 3;

    const u32 aA = sb + OF_A + (mrow + rr + ((q & 1) << 3)) * 528 + (((q >> 1) << 3) << 1);

    // ---- GEMM1: warp = m16 x n16, K=256, single fp16 pass
    float D1[2][4];
    #pragma unroll
    for (int nt = 0; nt < 2; ++nt)
        #pragma unroll
        for (int r = 0; r < 4; ++r) D1[nt][r] = 0.f;

    const int r0 = (nw << 4) + rr + b_rowq;
    #pragma unroll 8
    for (int kt = 0; kt < 16; ++kt) {
        u32 a[4], b[4];
        ldm4(a, aA + (kt << 5));
        ldm4(b, sb + OF_B1 + (kt << 5) + (b_colq << 1) + r0 * 528);
        mma_f16(D1[0], a, b[0], b[1]);
        mma_f16(D1[1], a, b[2], b[3]);
    }

    // ---- epilogue 1: relu(D1 + bo1) -> fp16 g in smem
    {
        const float* sb1f = (const float*)(smc + OF_SB1);
        #pragma unroll
        for (int nt = 0; nt < 2; ++nt) {
            const int col = (nw << 4) + (nt << 3) + (tq << 1);
            const float bv0 = sb1f[col], bv1 = sb1f[col + 1];
            const u32 w0 = (u32)f2h(fmaxf(D1[nt][0] + bv0, 0.f)) |
                           ((u32)f2h(fmaxf(D1[nt][1] + bv1, 0.f)) << 16);
            const u32 w1v = (u32)f2h(fmaxf(D1[nt][2] + bv0, 0.f)) |
                            ((u32)f2h(fmaxf(D1[nt][3] + bv1, 0.f)) << 16);
            const int c2 = col << 1;     // byte offset
            *(u32*)(smc + OF_G + (mrow + gg) * 144 + c2)     = w0;
            *(u32*)(smc + OF_G + (mrow + gg + 8) * 144 + c2) = w1v;
        }
    }
    __syncthreads();

    // ---- GEMM2: warp = m16 x n64 (8 ntiles), K=64, single fp16 pass
    float D2[8][4];
    #pragma unroll
    for (int nt = 0; nt < 8; ++nt)
        #pragma unroll
        for (int r = 0; r < 4; ++r) D2[nt][r] = 0.f;

    const u32 gA = sb + OF_G + (mrow + rr + ((q & 1) << 3)) * 144;
    #pragma unroll
    for (int j = 0; j < 4; ++j) {
        u32 a2[4];
        ldm4(a2, gA + (((j << 4) + ((q >> 1) << 3)) << 1));
        #pragma unroll
        for (int cp = 0; cp < 2; ++cp) {
            const int c0r = (nw << 6) + (cp << 5) + rr + b_rowq;
            const u32 bb = sb + OF_B2 + (j << 5) + (b_colq << 1);
            u32 bh0[4], bh1[4];
            ldm4(bh0, bb + c0r * 144);
            ldm4(bh1, bb + (c0r + 16) * 144);
            float* d0 = D2[(cp << 2) + 0];
            float* d1 = D2[(cp << 2) + 1];
            float* d2 = D2[(cp << 2) + 2];
            float* d3 = D2[(cp << 2) + 3];
            mma_f16(d0, a2, bh0[0], bh0[1]);
            mma_f16(d1, a2, bh0[2], bh0[3]);
            mma_f16(d2, a2, bh1[0], bh1[1]);
            mma_f16(d3, a2, bh1[2], bh1[3]);
        }
    }

    // ---- store out + bo2
    {
        const float* sb2f = (const float*)(smc + OF_SB2);
        #pragma unroll
        for (int nt = 0; nt < 8; ++nt) {
            const int ob = (nw << 6) + (nt << 3);
            const float bv0 = sb2f[ob + (tq << 1)];
            const float bv1 = sb2f[ob + (tq << 1) + 1];
            const int row = b0 + mrow + gg;
            *(float2*)(out + (size_t)row * ONn + ob + (tq << 1)) =
                make_float2(D2[nt][0] + bv0, D2[nt][1] + bv1);
            *(float2*)(out + (size_t)(row + 8) * ONn + ob + (tq << 1)) =
                make_float2(D2[nt][2] + bv0, D2[nt][3] + bv1);
        }
    }
}

// ---------------------------------------------------------------------------
extern "C" void kernel_launch(void* const* d_in, const int* in_sizes, int n_in,
                              void* d_out, int out_size)
{
    const float* x   = (const float*)d_in[0];
    const float* w1  = (const float*)d_in[1];
    const float* b1  = (const float*)d_in[2];
    const float* w2  = (const float*)d_in[3];
    const float* b2  = (const float*)d_in[4];
    const float* wo1 = (const float*)d_in[5];
    const float* bo1 = (const float*)d_in[6];
    const float* wo2 = (const float*)d_in[7];
    const float* bo2 = (const float*)d_in[8];
    float* out = (float*)d_out;

    cudaFuncSetAttribute(kan_eval, cudaFuncAttributeMaxDynamicSharedMemorySize, EVAL_SMEM);
    cudaFuncSetAttribute(kan_mma,  cudaFuncAttributeMaxDynamicSharedMemorySize, MMA_SMEM);

    kan_eval<<<dim3(Bn / 512, Dn / 16), 256, EVAL_SMEM>>>(x, w1, b1, w2, b2, wo1, wo2);
    kan_mma<<<Bn / 32, 256, MMA_SMEM>>>(bo1, bo2, out);
}

// round 15
// speedup vs baseline: 1.4900x; 1.2049x over previous
#include <cuda_runtime.h>
#include <cuda_fp16.h>
#include <cstdint>

#define Bn 8192
#define Dn 256
#define INn 64
#define ONn 256

typedef unsigned int u32;
typedef unsigned short u16;

// Fragment-ordered images (uint4 = the 4 .b32 regs one lane feeds to mma):
// A:  [btile 256][kt 16][mw 2][lane 32]  (a0,a1,a2,a3)
// W1: [chunk 4][kt 16][lane 32]          (b0,b1,b2,b3)
// W2: [chunk 16][j 4][lane 32]           (b0,b1,b2,b3)
__device__ __align__(16) uint4 g_Af[256 * 16 * 2 * 32];   // 4MB
__device__ __align__(16) uint4 g_W1f[4 * 16 * 32];
__device__ __align__(16) uint4 g_W2f[16 * 4 * 32];

__device__ __forceinline__ void mma_f16(float* d, const u32* a, u32 b0, u32 b1) {
    asm volatile("mma.sync.aligned.m16n8k16.row.col.f32.f16.f16.f32 "
                 "{%0,%1,%2,%3}, {%4,%5,%6,%7}, {%8,%9}, {%0,%1,%2,%3};"
                 : "+f"(d[0]), "+f"(d[1]), "+f"(d[2]), "+f"(d[3])
                 : "r"(a[0]), "r"(a[1]), "r"(a[2]), "r"(a[3]), "r"(b0), "r"(b1));
}
__device__ __forceinline__ u16 f2h(float v) {
    return __half_as_ushort(__float2half(v));
}
__device__ __forceinline__ u32 pk(float lo, float hi) {
    return (u32)f2h(lo) | ((u32)f2h(hi) << 16);
}

// ---------------------------------------------------------------------------
// kan_eval: PWL prep + eval (R14-verified core), emits A in FRAGMENT order.
// Block (bx,by): b range bx*512.., d range by*16.. (=> kt = by).
// bx==0 blocks also build fragment-ordered W1/W2 images.
// ---------------------------------------------------------------------------
#define R2OFF 3104
#define EVAL_SMEM ((R2OFF + 8320) * 4)

__global__ __launch_bounds__(256, 2) void kan_eval(
    const float* __restrict__ x,
    const float* __restrict__ w1, const float* __restrict__ b1,
    const float* __restrict__ w2, const float* __restrict__ b2,
    const float* __restrict__ wo1, const float* __restrict__ wo2)
{
    extern __shared__ float sm[];
    float*  sT  = sm;                        // [16][64]
    float2* sSC = (float2*)(sm + 1024);      // [16][65]
    float*  r2  = sm + R2OFF;
    float* skey = r2;                        // [16][65]
    float* ssK  = r2 + 3120;
    float* ssS  = r2 + 4160;
    float* ssC  = r2 + 5200;
    float* sx   = r2;                        // [16][520]
    u32*  stgA  = (u32*)r2;                  // [512][9]

    const int t = threadIdx.x;
    const int lane = t & 31, w = t >> 5;
    const int b0 = blockIdx.x << 9;
    const int d0 = blockIdx.y << 4;

    // ---- fragment-ordered weight images (16 bx==0 blocks, 1 uint4/thread each half)
    if (blockIdx.x == 0) {
        const int gid = (blockIdx.y << 8) + t;     // 0..4095
        if (gid < 2048) {
            // W1f: c = gid>>9, kt = (gid>>5)&15, l = gid&31
            const int c = gid >> 9, kt = (gid >> 5) & 15, l = gid & 31;
            const int n = (c << 4) + (l >> 2);
            const int k = (kt << 4) + ((l & 3) << 1);
            const float* p0 = wo1 + n * 256 + k;
            const float* p8 = wo1 + (n + 8) * 256 + k;
            g_W1f[gid] = make_uint4(pk(p0[0], p0[1]), pk(p0[8], p0[9]),
                                    pk(p8[0], p8[1]), pk(p8[8], p8[9]));
        } else {
            // W2f: e = gid-2048; c = e>>7, j = (e>>5)&3, l = e&31
            const int e = gid - 2048;
            const int c = e >> 7, j = (e >> 5) & 3, l = e & 31;
            const int n = (c << 4) + (l >> 2);
            const int k = (j << 4) + ((l & 3) << 1);
            const float* p0 = wo2 + n * 64 + k;
            const float* p8 = wo2 + (n + 8) * 64 + k;
            g_W2f[e] = make_uint4(pk(p0[0], p0[1]), pk(p0[8], p0[9]),
                                  pk(p8[0], p8[1]), pk(p8[8], p8[9]));
        }
    }

    // ---------------- Phase P: LUT build (R12/R14-verified) ----------------
    const int dl = t >> 4;
    const int i0 = (t & 15) << 2;
    float key[4], dS[4], dC[4];
    float myBS = 0.f, myBC = 0.f;
    {
        const int base = (d0 + dl) * INn + i0;
        const float4 w4 = *(const float4*)(w1 + base);
        const float4 b4 = *(const float4*)(b1 + base);
        const float4 v4 = *(const float4*)(w2 + base);
        const float* wf = (const float*)&w4;
        const float* bf = (const float*)&b4;
        const float* vf = (const float*)&v4;
        #pragma unroll
        for (int q = 0; q < 4; ++q) {
            const float ww = wf[q], bb = bf[q], vv = vf[q];
            if (ww == 0.f) {
                key[q] = __int_as_float(0x7f800000);
                dS[q] = 0.f; dC[q] = 0.f;
                myBC += fmaxf(bb, 0.f) * vv;
            } else {
                key[q] = -bb / ww;
                const float pS = ww * vv, pC = bb * vv;
                if (ww > 0.f) { dS[q] = pS;  dC[q] = pC; }
                else          { dS[q] = -pS; dC[q] = -pC; myBS += pS; myBC += pC; }
            }
            skey[dl * 65 + i0 + q] = key[q];
        }
    }
    #pragma unroll
    for (int off = 8; off >= 1; off >>= 1) {
        myBS += __shfl_xor_sync(~0u, myBS, off);
        myBC += __shfl_xor_sync(~0u, myBC, off);
    }
    __syncthreads();

    #pragma unroll
    for (int q = 0; q < 4; ++q) {
        const float kq = key[q];
        const int iq = i0 + q;
        int rank = 0;
        const float* row = skey + dl * 65;
        #pragma unroll
        for (int j = 0; j < 64; ++j) {
            const float tj = row[j];
            rank += (tj < kq || (tj == kq && j < iq)) ? 1 : 0;
        }
        ssK[dl * 65 + rank] = kq;
        ssS[dl * 65 + rank] = dS[q];
        ssC[dl * 65 + rank] = dC[q];
    }
    __syncthreads();

    #pragma unroll
    for (int h = 0; h < 2; ++h) {
        const int dd = (w << 1) + h;
        float s0 = ssS[dd * 65 + lane], s1 = ssS[dd * 65 + lane + 32];
        float c0 = ssC[dd * 65 + lane], c1 = ssC[dd * 65 + lane + 32];
        #pragma unroll
        for (int off = 1; off < 32; off <<= 1) {
            const float a0 = __shfl_up_sync(~0u, s0, off);
            const float a1 = __shfl_up_sync(~0u, c0, off);
            const float a2 = __shfl_up_sync(~0u, s1, off);
            const float a3 = __shfl_up_sync(~0u, c1, off);
            if (lane >= off) { s0 += a0; c0 += a1; s1 += a2; c1 += a3; }
        }
        s1 += __shfl_sync(~0u, s0, 31);
        c1 += __shfl_sync(~0u, c0, 31);
        float bS = __shfl_sync(~0u, myBS, h << 4);
        float bC = __shfl_sync(~0u, myBC, h << 4);
        bC += __ldg(b2 + d0 + dd);
        sT[(dd << 6) + lane]      = ssK[dd * 65 + lane];
        sT[(dd << 6) + lane + 32] = ssK[dd * 65 + lane + 32];
        if (lane == 0) sSC[dd * 65] = make_float2(bS, bC);
        sSC[dd * 65 + 1 + lane]  = make_float2(bS + s0, bC + c0);
        sSC[dd * 65 + 33 + lane] = make_float2(bS + s1, bC + c1);
    }
    __syncthreads();

    // ---------------- Phase E ----------------
    for (int k = t; k < 2048; k += 256) {
        const int b = k >> 2, c4 = (k & 3) << 2;
        const float4 v = *(const float4*)(x + (size_t)(b0 + b) * Dn + d0 + c4);
        sx[(c4 + 0) * 520 + b] = v.x;
        sx[(c4 + 1) * 520 + b] = v.y;
        sx[(c4 + 2) * 520 + b] = v.z;
        sx[(c4 + 3) * 520 + b] = v.w;
    }
    __syncthreads();

    const int dA = w << 1, dB = dA + 1;
    const float*  ttA = sT + (dA << 6);
    const float*  ttB = sT + (dB << 6);
    const float2* scA = sSC + dA * 65;
    const float2* scB = sSC + dB * 65;
    u32 packA[16];
    #pragma unroll
    for (int ch = 0; ch < 16; ++ch) {
        const int b = (ch << 5) + lane;
        const float xa = sx[dA * 520 + b];
        const float xb = sx[dB * 520 + b];
        int p = 0;
        p += (ttA[31]     <= xa) ? 32 : 0;
        p += (ttA[p + 15] <= xa) ? 16 : 0;
        p += (ttA[p + 7]  <= xa) ? 8  : 0;
        p += (ttA[p + 3]  <= xa) ? 4  : 0;
        p += (ttA[p + 1]  <= xa) ? 2  : 0;
        p += (ttA[p]      <= xa) ? 1  : 0;
        p += (ttA[p]      <= xa) ? 1  : 0;
        int r = 0;
        r += (ttB[31]     <= xb) ? 32 : 0;
        r += (ttB[r + 15] <= xb) ? 16 : 0;
        r += (ttB[r + 7]  <= xb) ? 8  : 0;
        r += (ttB[r + 3]  <= xb) ? 4  : 0;
        r += (ttB[r + 1]  <= xb) ? 2  : 0;
        r += (ttB[r]      <= xb) ? 1  : 0;
        r += (ttB[r]      <= xb) ? 1  : 0;
        const float2 sa = scA[p];
        const float2 sb2 = scB[r];
        const float va = fmaf(sa.x, xa, sa.y);
        const float vb = fmaf(sb2.x, xb, sb2.y);
        packA[ch] = ((u32)f2h(vb) << 16) | f2h(va);   // low = even d (k)
    }
    __syncthreads();   // sx dead -> staging

    #pragma unroll
    for (int ch = 0; ch < 16; ++ch) {
        const int b = (ch << 5) + lane;
        stgA[b * 9 + w] = packA[ch];
    }
    __syncthreads();

    // ---- fragment-ordered A store: uint4 = (a0,a1,a2,a3) for (btile, kt=by, mw, lane)
    for (int idx = t; idx < 1024; idx += 256) {
        const int tt = idx >> 6, mw = (idx >> 5) & 1, l = idx & 31;
        const int gg = l >> 2, tq = l & 3;
        const int bl = (tt << 5) + (mw << 4) + gg;
        const u32 u0 = stgA[bl * 9 + tq];
        const u32 u1 = stgA[(bl + 8) * 9 + tq];
        const u32 u2 = stgA[bl * 9 + tq + 4];
        const u32 u3 = stgA[(bl + 8) * 9 + tq + 4];
        const int bt = (blockIdx.x << 4) + tt;
        g_Af[(((bt << 4) + blockIdx.y) << 6) + (mw << 5) + l] =
            make_uint4(u0, u1, u2, u3);
    }
}

// ---------------------------------------------------------------------------
// kan_mma v5: fragment-direct. No ldmatrix, no weight staging; smem = 4KB g
// exchange + biases. btile 32, grid 256, 256 threads (2 mw x 4 nw warps).
// GEMM1: 16 kt x (2 LDG.128 + 2 mma). Exchange: STS.128 + bar + LDS.128.
// GEMM2: 4 j x (LDS.128 + 2 x (2 LDG.128 + 4 mma)).
// ---------------------------------------------------------------------------
__global__ __launch_bounds__(256, 3) void kan_mma(
    const float* __restrict__ bo1, const float* __restrict__ bo2,
    float* __restrict__ out)
{
    __shared__ uint4 gfr[2][4][32];
    __shared__ float sb1[64];
    __shared__ float sb2[256];

    const int t = threadIdx.x;
    const int bt = blockIdx.x;
    const int b0 = bt << 5;

    if (t < 64) sb1[t] = __ldg(bo1 + t);
    if (t < 128) {
        sb2[t] = __ldg(bo2 + t);
        sb2[t + 128] = __ldg(bo2 + t + 128);
    }
    __syncthreads();

    const int w = t >> 5, lane = t & 31;
    const int mw = w & 1, nw = w >> 1;
    const int mrow = mw << 4;
    const int tq = lane & 3, gg = lane >> 2;

    // ---- GEMM1: warp = m16 x n16, K=256
    float D1[2][4] = {};
    const uint4* aP = g_Af + (bt << 10) + (mw << 5) + lane;   // + kt*64
    const uint4* bP = g_W1f + (nw << 9) + lane;               // + kt*32
    #pragma unroll 4
    for (int kt = 0; kt < 16; ++kt) {
        const uint4 av = aP[kt << 6];
        const uint4 bv = bP[kt << 5];
        u32 a[4] = {av.x, av.y, av.z, av.w};
        mma_f16(D1[0], a, bv.x, bv.y);
        mma_f16(D1[1], a, bv.z, bv.w);
    }

    // ---- epilogue 1: relu(D1 + bo1), pack into A2-fragment order
    {
        const int col = (nw << 4) + (tq << 1);
        const float bvA = sb1[col],     bvB = sb1[col + 1];
        const float bvC = sb1[col + 8], bvD = sb1[col + 9];
        const u32 u0 = pk(fmaxf(D1[0][0] + bvA, 0.f), fmaxf(D1[0][1] + bvB, 0.f));
        const u32 u1 = pk(fmaxf(D1[0][2] + bvA, 0.f), fmaxf(D1[0][3] + bvB, 0.f));
        const u32 u2 = pk(fmaxf(D1[1][0] + bvC, 0.f), fmaxf(D1[1][1] + bvD, 0.f));
        const u32 u3 = pk(fmaxf(D1[1][2] + bvC, 0.f), fmaxf(D1[1][3] + bvD, 0.f));
        gfr[mw][nw][lane] = make_uint4(u0, u1, u2, u3);
    }
    __syncthreads();

    // ---- GEMM2: warp = m16 x n64, K=64
    float D2[8][4] = {};
    #pragma unroll
    for (int j = 0; j < 4; ++j) {
        const uint4 ga = gfr[mw][j][lane];
        u32 a2[4] = {ga.x, ga.y, ga.z, ga.w};
        #pragma unroll
        for (int cp = 0; cp < 2; ++cp) {
            const int c0 = (nw << 2) + (cp << 1);
            const uint4 b0v = g_W2f[(((c0 << 2) + j) << 5) + lane];
            const uint4 b1v = g_W2f[((((c0 + 1) << 2) + j) << 5) + lane];
            float* d0 = D2[(cp << 2) + 0];
            float* d1 = D2[(cp << 2) + 1];
            float* d2 = D2[(cp << 2) + 2];
            float* d3 = D2[(cp << 2) + 3];
            mma_f16(d0, a2, b0v.x, b0v.y);
            mma_f16(d1, a2, b0v.z, b0v.w);
            mma_f16(d2, a2, b1v.x, b1v.y);
            mma_f16(d3, a2, b1v.z, b1v.w);
        }
    }

    // ---- store out + bo2
    #pragma unroll
    for (int nt = 0; nt < 8; ++nt) {
        const int ob = (nw << 6) + (nt << 3);
        const float bv0 = sb2[ob + (tq << 1)];
        const float bv1 = sb2[ob + (tq << 1) + 1];
        const int row = b0 + mrow + gg;
        *(float2*)(out + (size_t)row * ONn + ob + (tq << 1)) =
            make_float2(D2[nt][0] + bv0, D2[nt][1] + bv1);
        *(float2*)(out + (size_t)(row + 8) * ONn + ob + (tq << 1)) =
            make_float2(D2[nt][2] + bv0, D2[nt][3] + bv1);
    }
}

// ---------------------------------------------------------------------------
extern "C" void kernel_launch(void* const* d_in, const int* in_sizes, int n_in,
                              void* d_out, int out_size)
{
    const float* x   = (const float*)d_in[0];
    const float* w1  = (const float*)d_in[1];
    const float* b1  = (const float*)d_in[2];
    const float* w2  = (const float*)d_in[3];
    const float* b2  = (const float*)d_in[4];
    const float* wo1 = (const float*)d_in[5];
    const float* bo1 = (const float*)d_in[6];
    const float* wo2 = (const float*)d_in[7];
    const float* bo2 = (const float*)d_in[8];
    float* out = (float*)d_out;

    cudaFuncSetAttribute(kan_eval, cudaFuncAttributeMaxDynamicSharedMemorySize, EVAL_SMEM);

    kan_eval<<<dim3(Bn / 512, Dn / 16), 256, EVAL_SMEM>>>(x, w1, b1, w2, b2, wo1, wo2);
    kan_mma<<<Bn / 32, 256>>>(bo1, bo2, out);
}